// round 15
// baseline (speedup 1.0000x reference)
#include <cuda_runtime.h>
#include <cuda_fp16.h>
#include <math.h>
#include <cstdint>

#define HD 450
#define HDP 464
#define NTREE 32
#define NB 1024
#define NNODE (NB*NTREE)
#define NV 780

// ---------------- scratch ----------------
__device__ float g_pz [NV*HD];
__device__ float g_ph [NV*HD];
__device__ float g_pr [NV*HD];
__device__ float g_pgt[NV*HD];
__device__ float g_mlf[NV*HD];
__device__ float g_rur[NV*HD];
__device__ float g_m  [NNODE*HD];
__device__ float g_rm [NNODE*HD];
__device__ float g_s32[NB*8*HD];      // child-sum s, fp32 (for m_new epilogue)
// fp16 activations (stride HDP, zero-padded)
__device__ __half g_ef  [NV*HDP];
__device__ __half g_mlff[NV*HDP];
__device__ __half g_sf  [NB*8*HDP];
__device__ __half g_af  [NB*8*HDP];
__device__ __half g_mdf [NB*8*HDP];
// fp16 weights, split hi/lo
__device__ __half g_wh  [8*HD*HDP];
__device__ __half g_wl  [8*HD*HDP];
// slots: 0 Wz_top, 1 Wz_bot, 2 Wh_top, 3 Wh_bot, 4 Wr, 5 Ur, 6 Wg_top, 7 Wg_bot

// ================= helpers =================
constexpr int BM = 128, BN = 64, BK = 64;
constexpr int NCHK = 8;
constexpr int ASTR = 72;
constexpr int BSTR = 72;
constexpr int STG  = BM*ASTR + 2*BK*BSTR;       // 18432 halfs
constexpr int NSTG = 3;
constexpr int SMEMB = NSTG * STG * 2;           // 110592 B
constexpr int STGZ = 2*BM*ASTR + 4*BK*BSTR;     // 36864 halfs (zhm stage)
constexpr int SMEMZ = 2 * STGZ * 2;             // 147456 B

__device__ __forceinline__ void ldm_x4(uint32_t* r, uint32_t addr) {
    asm volatile("ldmatrix.sync.aligned.m8n8.x4.shared.b16 {%0,%1,%2,%3}, [%4];"
                 : "=r"(r[0]), "=r"(r[1]), "=r"(r[2]), "=r"(r[3]) : "r"(addr));
}
__device__ __forceinline__ void ldm_x4t(uint32_t* r, uint32_t addr) {
    asm volatile("ldmatrix.sync.aligned.m8n8.x4.trans.shared.b16 {%0,%1,%2,%3}, [%4];"
                 : "=r"(r[0]), "=r"(r[1]), "=r"(r[2]), "=r"(r[3]) : "r"(addr));
}
__device__ __forceinline__ void mma_fp16(float* c, const uint32_t* a, const uint32_t* b) {
    asm volatile("mma.sync.aligned.m16n8k16.row.col.f32.f16.f16.f32 "
                 "{%0,%1,%2,%3}, {%4,%5,%6,%7}, {%8,%9}, {%0,%1,%2,%3};"
                 : "+f"(c[0]), "+f"(c[1]), "+f"(c[2]), "+f"(c[3])
                 : "r"(a[0]), "r"(a[1]), "r"(a[2]), "r"(a[3]), "r"(b[0]), "r"(b[1]));
}
__device__ __forceinline__ void cp16(uint32_t smem, const void* g) {
    asm volatile("cp.async.cg.shared.global [%0], [%1], 16;" :: "r"(smem), "l"(g));
}
#define CP_COMMIT() asm volatile("cp.async.commit_group;")
#define CP_WAITG1() asm volatile("cp.async.wait_group 1;" ::: "memory")

__device__ __forceinline__ uint32_t pack2h(float2 v) {
    __half2 h = __floats2half2_rn(v.x, v.y);
    return *(uint32_t*)&h;
}
__device__ __forceinline__ void split2h(float2 v, uint32_t& hi, uint32_t& lo) {
    __half2 h = __floats2half2_rn(v.x, v.y);
    float rx = v.x - __half2float(__low2half(h));
    float ry = v.y - __half2float(__high2half(h));
    __half2 l = __floats2half2_rn(rx, ry);
    hi = *(uint32_t*)&h;
    lo = *(uint32_t*)&l;
}
__device__ __forceinline__ float sigf(float x) { return 1.f / (1.f + expf(-x)); }

// ================= single-source GEMM body (r13/r14, proven) =================
// EPI: 0 plain; 1 +bias; 3 rm=sig(pr[wp]+acc)*msrc; 4 relu(ptab[w0]+acc)
template<int EPI>
__device__ __forceinline__ void gemm_body(
    const __half* __restrict__ Ag,
    const __half* __restrict__ Bgh, const __half* __restrict__ Bgl,
    const float* __restrict__ bias, float* __restrict__ C,
    int M, int lo, int lg,
    const int* __restrict__ wid, const float* __restrict__ ptab,
    const float* __restrict__ pr, const float* __restrict__ msrc)
{
    extern __shared__ __align__(16) __half smp[];
    const int tid = threadIdx.x;
    const int lane = tid & 31, wrp = tid >> 5;
    const int wm = wrp & 3, wn = wrp >> 2;
    const int n0 = blockIdx.x * BN, m0 = blockIdx.y * BM;

    float acc[2][4][4] = {};

    const int q = lane >> 3, r8 = lane & 7;
    const int arow_off = (q & 1) * 8 + r8;
    const int acol_off = (q >> 1) * 8;
    const int l16 = lane & 15;
    const int bcol8 = ((lane >> 4) & 1) * 8;

    auto fill = [&](int s, int c) {
        __half* Asm = smp + s * STG;
        __half* Bh  = Asm + BM * ASTR;
        __half* Bl  = Bh + BK * BSTR;
#pragma unroll
        for (int i = 0; i < 4; i++) {
            int idx = tid + i * 256;
            int row = idx >> 3, seg = idx & 7;
            int k = c * BK + seg * 8;
            int arow = m0 + row;
            __half* d = Asm + row * ASTR + seg * 8;
            if (arow < M && k <= HDP - 8)
                cp16((uint32_t)__cvta_generic_to_shared(d), Ag + (size_t)arow * HDP + k);
            else
                *(uint4*)d = make_uint4(0, 0, 0, 0);
        }
#pragma unroll
        for (int i = 0; i < 2; i++) {
            int idx = tid + i * 256;
            int kk = idx >> 3, seg = idx & 7;
            int k = c * BK + kk;
            int nj = n0 + seg * 8;
            __half* dh = Bh + kk * BSTR + seg * 8;
            __half* dl = Bl + kk * BSTR + seg * 8;
            if (k < HD && nj <= HDP - 8) {
                size_t gofs = (size_t)k * HDP + nj;
                cp16((uint32_t)__cvta_generic_to_shared(dh), Bgh + gofs);
                cp16((uint32_t)__cvta_generic_to_shared(dl), Bgl + gofs);
            } else {
                *(uint4*)dh = make_uint4(0, 0, 0, 0);
                *(uint4*)dl = make_uint4(0, 0, 0, 0);
            }
        }
    };

    fill(0, 0); CP_COMMIT();
    fill(1, 1); CP_COMMIT();
    for (int c = 0; c < NCHK; c++) {
        CP_WAITG1();
        __syncthreads();
        if (c + 2 < NCHK) fill((c + 2) % NSTG, c + 2);
        CP_COMMIT();

        const uint32_t sA  = (uint32_t)__cvta_generic_to_shared(smp + (c % NSTG) * STG);
        const uint32_t sBh = sA + BM * ASTR * 2;
        const uint32_t sBl = sBh + BK * BSTR * 2;
#pragma unroll
        for (int ks = 0; ks < 4; ks++) {
            uint32_t ah[2][4], bh[4][2], bl[4][2];
#pragma unroll
            for (int mf = 0; mf < 2; mf++) {
                int row = wm * 32 + mf * 16 + arow_off;
                int col = ks * 16 + acol_off;
                ldm_x4(ah[mf], sA + (uint32_t)(row * ASTR + col) * 2);
            }
#pragma unroll
            for (int nfp = 0; nfp < 2; nfp++) {
                uint32_t off = (uint32_t)((ks * 16 + l16) * BSTR
                                          + wn * 32 + nfp * 16 + bcol8) * 2;
                uint32_t r4[4];
                ldm_x4t(r4, sBh + off);
                bh[2 * nfp][0] = r4[0]; bh[2 * nfp][1] = r4[1];
                bh[2 * nfp + 1][0] = r4[2]; bh[2 * nfp + 1][1] = r4[3];
                ldm_x4t(r4, sBl + off);
                bl[2 * nfp][0] = r4[0]; bl[2 * nfp][1] = r4[1];
                bl[2 * nfp + 1][0] = r4[2]; bl[2 * nfp + 1][1] = r4[3];
            }
#pragma unroll
            for (int mf = 0; mf < 2; mf++)
#pragma unroll
                for (int nf = 0; nf < 4; nf++) {
                    mma_fp16(acc[mf][nf], ah[mf], bh[nf]);
                    mma_fp16(acc[mf][nf], ah[mf], bl[nf]);
                }
        }
    }

    const int gr = lane >> 2, gc = (lane & 3) * 2;
#pragma unroll
    for (int mf = 0; mf < 2; mf++) {
#pragma unroll
        for (int h = 0; h < 2; h++) {
            int arow = m0 + wm * 32 + mf * 16 + h * 8 + gr;
            if (arow >= M) continue;
            int g = 0, wp = 0, w0 = 0;
            if constexpr (EPI == 3) {
                int t = arow >> lg, ci = lo + (arow & ((1 << lg) - 1));
                g  = t * NTREE + ci;
                wp = wid[t * NTREE + ((ci - 1) >> 1)];
            } else if constexpr (EPI == 4) {
                w0 = wid[arow * NTREE];
            }
#pragma unroll
            for (int nf = 0; nf < 4; nf++) {
                int j = n0 + wn * 32 + nf * 8 + gc;
                if (j >= HD) continue;
                float vx = acc[mf][nf][h * 2];
                float vy = acc[mf][nf][h * 2 + 1];
                if constexpr (EPI == 0) {
                    *(float2*)&C[arow * HD + j] = make_float2(vx, vy);
                } else if constexpr (EPI == 1) {
                    float2 b = *(const float2*)&bias[j];
                    *(float2*)&C[arow * HD + j] = make_float2(vx + b.x, vy + b.y);
                } else if constexpr (EPI == 3) {
                    float2 pv = *(const float2*)&pr[wp * HD + j];
                    float2 mv = *(const float2*)&msrc[g * HD + j];
                    *(float2*)&C[g * HD + j] =
                        make_float2(sigf(pv.x + vx) * mv.x, sigf(pv.y + vy) * mv.y);
                } else {
                    float2 pv = *(const float2*)&ptab[w0 * HD + j];
                    *(float2*)&C[arow * HD + j] =
                        make_float2(fmaxf(pv.x + vx, 0.f), fmaxf(pv.y + vy, 0.f));
                }
            }
        }
    }
}

// ================= fused z+h GEMM with m_new epilogue =================
// accz = s@Wz_bot, acch = arm@Wh_bot; m_new = (1-z)*s32 + z*tanh(ph+acch)
__global__ __launch_bounds__(256) void tc_zhm(
    const __half* __restrict__ Asf, const __half* __restrict__ Aaf,
    const __half* __restrict__ wzh, const __half* __restrict__ wzl,
    const __half* __restrict__ whh, const __half* __restrict__ whl,
    const int* __restrict__ wid,
    const float* __restrict__ pz, const float* __restrict__ ph_,
    const float* __restrict__ s32,
    float* __restrict__ m, __half* __restrict__ mdf,
    int M, int lo, int lg)
{
    extern __shared__ __align__(16) __half smp[];
    const int tid = threadIdx.x;
    const int lane = tid & 31, wrp = tid >> 5;
    const int wm = wrp & 3, wn = wrp >> 2;
    const int n0 = blockIdx.x * BN, m0 = blockIdx.y * BM;

    float acc[2][2][4][4] = {};   // [src][mf][nf][e]

    const int q = lane >> 3, r8 = lane & 7;
    const int arow_off = (q & 1) * 8 + r8;
    const int acol_off = (q >> 1) * 8;
    const int l16 = lane & 15;
    const int bcol8 = ((lane >> 4) & 1) * 8;

    const __half* Asrc[2] = {Asf, Aaf};
    const __half* Bhsrc[2] = {wzh, whh};
    const __half* Blsrc[2] = {wzl, whl};

    auto fill = [&](int s, int c) {
        __half* base = smp + s * STGZ;
        // A tiles: 2 sources x 128 rows x 8 segs
#pragma unroll
        for (int src = 0; src < 2; src++) {
            __half* Asm = base + src * BM * ASTR;
#pragma unroll
            for (int i = 0; i < 4; i++) {
                int idx = tid + i * 256;
                int row = idx >> 3, seg = idx & 7;
                int k = c * BK + seg * 8;
                int arow = m0 + row;
                __half* d = Asm + row * ASTR + seg * 8;
                if (arow < M && k <= HDP - 8)
                    cp16((uint32_t)__cvta_generic_to_shared(d),
                         Asrc[src] + (size_t)arow * HDP + k);
                else
                    *(uint4*)d = make_uint4(0, 0, 0, 0);
            }
        }
        // B tiles: 2 sources x hi/lo
        __half* Bb = base + 2 * BM * ASTR;
#pragma unroll
        for (int i = 0; i < 2; i++) {
            int idx = tid + i * 256;
            int kk = idx >> 3, seg = idx & 7;
            int k = c * BK + kk;
            int nj = n0 + seg * 8;
            bool ok = (k < HD && nj <= HDP - 8);
            size_t gofs = (size_t)k * HDP + nj;
#pragma unroll
            for (int src = 0; src < 2; src++) {
                __half* dh = Bb + (2 * src) * BK * BSTR + kk * BSTR + seg * 8;
                __half* dl = Bb + (2 * src + 1) * BK * BSTR + kk * BSTR + seg * 8;
                if (ok) {
                    cp16((uint32_t)__cvta_generic_to_shared(dh), Bhsrc[src] + gofs);
                    cp16((uint32_t)__cvta_generic_to_shared(dl), Blsrc[src] + gofs);
                } else {
                    *(uint4*)dh = make_uint4(0, 0, 0, 0);
                    *(uint4*)dl = make_uint4(0, 0, 0, 0);
                }
            }
        }
    };

    fill(0, 0);
    CP_COMMIT();
    for (int c = 0; c < NCHK; c++) {
        int st = c & 1;
        if (c + 1 < NCHK) fill(st ^ 1, c + 1);
        CP_COMMIT();
        CP_WAITG1();
        __syncthreads();

        const uint32_t sBase = (uint32_t)__cvta_generic_to_shared(smp + st * STGZ);
#pragma unroll
        for (int src = 0; src < 2; src++) {
            const uint32_t sA  = sBase + src * BM * ASTR * 2;
            const uint32_t sBh = sBase + (2 * BM * ASTR + 2 * src * BK * BSTR) * 2;
            const uint32_t sBl = sBh + BK * BSTR * 2;
#pragma unroll
            for (int ks = 0; ks < 4; ks++) {
                uint32_t ah[2][4], bh[4][2], bl[4][2];
#pragma unroll
                for (int mf = 0; mf < 2; mf++) {
                    int row = wm * 32 + mf * 16 + arow_off;
                    int col = ks * 16 + acol_off;
                    ldm_x4(ah[mf], sA + (uint32_t)(row * ASTR + col) * 2);
                }
#pragma unroll
                for (int nfp = 0; nfp < 2; nfp++) {
                    uint32_t off = (uint32_t)((ks * 16 + l16) * BSTR
                                              + wn * 32 + nfp * 16 + bcol8) * 2;
                    uint32_t r4[4];
                    ldm_x4t(r4, sBh + off);
                    bh[2 * nfp][0] = r4[0]; bh[2 * nfp][1] = r4[1];
                    bh[2 * nfp + 1][0] = r4[2]; bh[2 * nfp + 1][1] = r4[3];
                    ldm_x4t(r4, sBl + off);
                    bl[2 * nfp][0] = r4[0]; bl[2 * nfp][1] = r4[1];
                    bl[2 * nfp + 1][0] = r4[2]; bl[2 * nfp + 1][1] = r4[3];
                }
#pragma unroll
                for (int mf = 0; mf < 2; mf++)
#pragma unroll
                    for (int nf = 0; nf < 4; nf++) {
                        mma_fp16(acc[src][mf][nf], ah[mf], bh[nf]);
                        mma_fp16(acc[src][mf][nf], ah[mf], bl[nf]);
                    }
            }
        }
        __syncthreads();
    }

    // ---- epilogue: m_new ----
    const int gr = lane >> 2, gc = (lane & 3) * 2;
#pragma unroll
    for (int mf = 0; mf < 2; mf++) {
#pragma unroll
        for (int h = 0; h < 2; h++) {
            int arow = m0 + wm * 32 + mf * 16 + h * 8 + gr;
            if (arow >= M) continue;
            int t = arow >> lg, ci = lo + (arow & ((1 << lg) - 1));
            int g = t * NTREE + ci;
            int w = wid[g];
#pragma unroll
            for (int nf = 0; nf < 4; nf++) {
                int j = n0 + wn * 32 + nf * 8 + gc;
                if (j >= HD) continue;
                float2 pzv = *(const float2*)&pz[w * HD + j];
                float2 phv = *(const float2*)&ph_[w * HD + j];
                float2 sv  = *(const float2*)&s32[arow * HD + j];
                float zx = sigf(pzv.x + acc[0][mf][nf][h * 2]);
                float zy = sigf(pzv.y + acc[0][mf][nf][h * 2 + 1]);
                float tx = tanhf(phv.x + acc[1][mf][nf][h * 2]);
                float ty = tanhf(phv.y + acc[1][mf][nf][h * 2 + 1]);
                float2 o = make_float2((1.f - zx) * sv.x + zx * tx,
                                       (1.f - zy) * sv.y + zy * ty);
                *(float2*)&m[g * HD + j] = o;
                *(uint32_t*)&mdf[arow * HDP + j] = pack2h(o);
            }
        }
    }
}

// ================= GEMM wrappers =================
__global__ __launch_bounds__(256) void tc_vocab(
    const __half* ef, const __half* wh, const __half* wl,
    const float* bz, const float* bh_, const float* bU, const float* bg,
    float* pz, float* ph_, float* pr, float* pgt)
{
    const int SZ = HD * HDP;
    const float* b; float* C; int slot;
    switch (blockIdx.z) {
        case 0:  slot = 0; b = bz;  C = pz;  break;
        case 1:  slot = 2; b = bh_; C = ph_; break;
        case 2:  slot = 4; b = bU;  C = pr;  break;
        default: slot = 6; b = bg;  C = pgt; break;
    }
    gemm_body<1>(ef, wh + slot * SZ, wl + slot * SZ, b, C,
                 NV, 0, 0, nullptr, nullptr, nullptr, nullptr);
}

__global__ __launch_bounds__(256) void tc_rur(
    const __half* mlff, const __half* wh, const __half* wl, float* rur)
{
    const int SZ = HD * HDP;
    gemm_body<0>(mlff, wh + 5 * SZ, wl + 5 * SZ, nullptr, rur,
                 NV, 0, 0, nullptr, nullptr, nullptr, nullptr);
}

__global__ __launch_bounds__(256) void tc_ur(
    const __half* mdf, const __half* wh, const __half* wl,
    float* rm, int M, int lo, int lg,
    const int* wid, const float* pr, const float* msrc)
{
    const int SZ = HD * HDP;
    gemm_body<3>(mdf, wh + 5 * SZ, wl + 5 * SZ, nullptr, rm,
                 M, lo, lg, wid, nullptr, pr, msrc);
}

__global__ __launch_bounds__(256) void tc_fin(
    const __half* sf, const __half* wh, const __half* wl,
    float* out, const int* wid, const float* pgt)
{
    const int SZ = HD * HDP;
    gemm_body<4>(sf, wh + 7 * SZ, wl + 7 * SZ, nullptr, out,
                 NB, 0, 0, wid, pgt, nullptr, nullptr);
}

// ================= producers =================
__global__ void preconv_k(const float* __restrict__ Wz, const float* __restrict__ Wh,
                          const float* __restrict__ Wr, const float* __restrict__ Ur,
                          const float* __restrict__ Wg,
                          __half* __restrict__ wh, __half* __restrict__ wl)
{
    int idx = blockIdx.x * blockDim.x + threadIdx.x;
    const int SZ2 = HD * HDP / 2;
    if (idx >= 8 * SZ2) return;
    int slot = idx / SZ2, off = idx - slot * SZ2;
    int k = off / (HDP / 2), j = (off - k * (HDP / 2)) * 2;
    float2 v = make_float2(0.f, 0.f);
    if (j < HD) {
        int src = k * HD + j;
        const int WSZ = HD * HD;
        switch (slot) {
            case 0:  v = *(const float2*)&Wz[src];       break;
            case 1:  v = *(const float2*)&Wz[WSZ + src]; break;
            case 2:  v = *(const float2*)&Wh[src];       break;
            case 3:  v = *(const float2*)&Wh[WSZ + src]; break;
            case 4:  v = *(const float2*)&Wr[src];       break;
            case 5:  v = *(const float2*)&Ur[src];       break;
            case 6:  v = *(const float2*)&Wg[src];       break;
            default: v = *(const float2*)&Wg[WSZ + src]; break;
        }
    }
    uint32_t hi, lo;
    split2h(v, hi, lo);
    int d = slot * HD * HDP + k * HDP + j;
    *(uint32_t*)&wh[d] = hi;
    *(uint32_t*)&wl[d] = lo;
}

__global__ void esplit_k(const float* __restrict__ emb, __half* __restrict__ ef)
{
    int idx = blockIdx.x * blockDim.x + threadIdx.x;
    if (idx >= NV * HDP / 2) return;
    int row = idx / (HDP / 2), j = (idx - row * (HDP / 2)) * 2;
    float2 v = (j < HD) ? *(const float2*)&emb[row * HD + j] : make_float2(0.f, 0.f);
    *(uint32_t*)&ef[row * HDP + j] = pack2h(v);
}

__global__ void mleaf_k(const float* __restrict__ pz, const float* __restrict__ ph,
                        float* __restrict__ mlf, __half* __restrict__ mlff)
{
    int idx = blockIdx.x * blockDim.x + threadIdx.x;
    if (idx >= NV * HDP / 2) return;
    int row = idx / (HDP / 2), j = (idx - row * (HDP / 2)) * 2;
    float2 v = make_float2(0.f, 0.f);
    if (j < HD) {
        int s = row * HD + j;
        float2 a = *(const float2*)&pz[s];
        float2 b = *(const float2*)&ph[s];
        v.x = tanhf(b.x) * sigf(a.x);
        v.y = tanhf(b.y) * sigf(a.y);
        *(float2*)&mlf[s] = v;
    }
    *(uint32_t*)&mlff[row * HDP + j] = pack2h(v);
}

// zero the padding columns of mdf once (j in [448, 464))
__global__ void padzero_k(__half* __restrict__ mdf)
{
    int idx = blockIdx.x * blockDim.x + threadIdx.x;
    const int PADW = (HDP - 448) / 2;   // 8 uint32 per row
    if (idx >= NB * 8 * PADW) return;
    int row = idx / PADW, c = idx - row * PADW;
    *(uint32_t*)&mdf[row * HDP + 448 + c * 2] = 0;
}

// s/arm for node 15 (single leaf child 31); writes s32 + sf + af
__global__ void s0_k(const int* __restrict__ wid,
                     const float* __restrict__ pr, const float* __restrict__ rur,
                     const float* __restrict__ mlf,
                     float* __restrict__ s32,
                     __half* __restrict__ sf, __half* __restrict__ af)
{
    int idx = blockIdx.x * blockDim.x + threadIdx.x;
    if (idx >= NB * (HDP / 2)) return;
    int t = idx / (HDP / 2), j = (idx - t * (HDP / 2)) * 2;
    float2 s = make_float2(0.f, 0.f), a = s;
    if (j < HD) {
        int w15 = wid[t * NTREE + 15];
        int w31 = wid[t * NTREE + 31];
        s = *(const float2*)&mlf[w31 * HD + j];
        float2 ru = *(const float2*)&rur[w31 * HD + j];
        float2 pv = *(const float2*)&pr[w15 * HD + j];
        a = make_float2(sigf(pv.x + ru.x) * s.x, sigf(pv.y + ru.y) * s.y);
        *(float2*)&s32[t * HD + j] = s;
    }
    int d = t * HDP + j;
    *(uint32_t*)&sf[d] = pack2h(s);
    *(uint32_t*)&af[d] = pack2h(a);
}

// sum s & arm for nodes [LO,LO+CNT): interior children from m/rm, leaves from tables
template<int LO, int CNT>
__global__ void sumarm_k(const int* __restrict__ wid,
                         const float* __restrict__ pr, const float* __restrict__ rur,
                         const float* __restrict__ mlf,
                         const float* __restrict__ m, const float* __restrict__ rm,
                         float* __restrict__ s32,
                         __half* __restrict__ sf, __half* __restrict__ af)
{
    int idx = blockIdx.x * blockDim.x + threadIdx.x;
    if (idx >= NB * CNT * (HDP / 2)) return;
    int row = idx / (HDP / 2), j = (idx - row * (HDP / 2)) * 2;
    int t = row / CNT;
    int n = LO + (row - t * CNT);
    float2 s = make_float2(0.f, 0.f), a = s;
    if (j < HD) {
        int wp = wid[t * NTREE + n];
#pragma unroll
        for (int ch = 0; ch < 2; ch++) {
            int c = 2 * n + 1 + ch;
            if (c < 16) {
                float2 mv = *(const float2*)&m[(t * NTREE + c) * HD + j];
                float2 rv = *(const float2*)&rm[(t * NTREE + c) * HD + j];
                s.x += mv.x; s.y += mv.y;
                a.x += rv.x; a.y += rv.y;
            } else {
                int w = wid[t * NTREE + c];
                float2 mv = *(const float2*)&mlf[w * HD + j];
                float2 ru = *(const float2*)&rur[w * HD + j];
                float2 pv = *(const float2*)&pr[wp * HD + j];
                s.x += mv.x; s.y += mv.y;
                a.x += sigf(pv.x + ru.x) * mv.x;
                a.y += sigf(pv.y + ru.y) * mv.y;
            }
        }
        *(float2*)&s32[row * HD + j] = s;
    }
    int d = row * HDP + j;
    *(uint32_t*)&sf[d] = pack2h(s);
    *(uint32_t*)&af[d] = pack2h(a);
}

// root s = m[1]+m[2] -> sf only
__global__ void sroot_k(const float* __restrict__ m, __half* __restrict__ sf)
{
    int idx = blockIdx.x * blockDim.x + threadIdx.x;
    if (idx >= NB * (HDP / 2)) return;
    int t = idx / (HDP / 2), j = (idx - t * (HDP / 2)) * 2;
    float2 s = make_float2(0.f, 0.f);
    if (j < HD) {
        float2 a = *(const float2*)&m[(t * NTREE + 1) * HD + j];
        float2 b = *(const float2*)&m[(t * NTREE + 2) * HD + j];
        s = make_float2(a.x + b.x, a.y + b.y);
    }
    *(uint32_t*)&sf[t * HDP + j] = pack2h(s);
}

// ================= launch =================
extern "C" void kernel_launch(void* const* d_in, const int* in_sizes, int n_in,
                              void* d_out, int out_size)
{
    const int*   wid = (const int*)  d_in[0];
    const float* emb = (const float*)d_in[1];
    const float* Wz  = (const float*)d_in[2];
    const float* bz  = (const float*)d_in[3];
    const float* Wr  = (const float*)d_in[4];
    const float* Ur  = (const float*)d_in[5];
    const float* bU  = (const float*)d_in[6];
    const float* Wh  = (const float*)d_in[7];
    const float* bh  = (const float*)d_in[8];
    const float* Wg  = (const float*)d_in[9];
    const float* bg  = (const float*)d_in[10];
    float* out = (float*)d_out;

    float *pz, *ph, *pr, *pgt, *mlf, *rur, *m, *rm, *s32;
    __half *ef, *mlff, *sf, *af, *mdf, *wh, *wl;
    cudaGetSymbolAddress((void**)&pz,  g_pz);
    cudaGetSymbolAddress((void**)&ph,  g_ph);
    cudaGetSymbolAddress((void**)&pr,  g_pr);
    cudaGetSymbolAddress((void**)&pgt, g_pgt);
    cudaGetSymbolAddress((void**)&mlf, g_mlf);
    cudaGetSymbolAddress((void**)&rur, g_rur);
    cudaGetSymbolAddress((void**)&m,   g_m);
    cudaGetSymbolAddress((void**)&rm,  g_rm);
    cudaGetSymbolAddress((void**)&s32, g_s32);
    cudaGetSymbolAddress((void**)&ef,  g_ef);
    cudaGetSymbolAddress((void**)&mlff, g_mlff);
    cudaGetSymbolAddress((void**)&sf,  g_sf);
    cudaGetSymbolAddress((void**)&af,  g_af);
    cudaGetSymbolAddress((void**)&mdf, g_mdf);
    cudaGetSymbolAddress((void**)&wh,  g_wh);
    cudaGetSymbolAddress((void**)&wl,  g_wl);

    cudaFuncSetAttribute(tc_vocab, cudaFuncAttributeMaxDynamicSharedMemorySize, SMEMB);
    cudaFuncSetAttribute(tc_rur,   cudaFuncAttributeMaxDynamicSharedMemorySize, SMEMB);
    cudaFuncSetAttribute(tc_ur,    cudaFuncAttributeMaxDynamicSharedMemorySize, SMEMB);
    cudaFuncSetAttribute(tc_fin,   cudaFuncAttributeMaxDynamicSharedMemorySize, SMEMB);
    cudaFuncSetAttribute(tc_zhm,   cudaFuncAttributeMaxDynamicSharedMemorySize, SMEMZ);

    const int NX = (HD + BN - 1) / BN;   // 8
    auto yb = [](int M) { return (M + BM - 1) / BM; };
    auto gb = [](int n) { return (n + 255) / 256; };

    // prelude
    preconv_k<<<gb(8 * HD * HDP / 2), 256>>>(Wz, Wh, Wr, Ur, Wg, wh, wl);
    esplit_k<<<gb(NV * HDP / 2), 256>>>(emb, ef);
    tc_vocab<<<dim3(NX, yb(NV), 4), 256, SMEMB>>>(ef, wh, wl,
                                                  bz, bh, bU, bg, pz, ph, pr, pgt);
    mleaf_k<<<gb(NV * HDP / 2), 256>>>(pz, ph, mlf, mlff);
    tc_rur<<<dim3(NX, yb(NV)), 256, SMEMB>>>(mlff, wh, wl, rur);
    padzero_k<<<gb(NB * 8 * 8), 256>>>(mdf);

    const int SZ = HD * HDP;
    // L0: node 15
    s0_k<<<gb(NB * HDP / 2), 256>>>(wid, pr, rur, mlf, s32, sf, af);
    tc_zhm<<<dim3(NX, yb(NB)), 256, SMEMZ>>>(sf, af, wh + SZ, wl + SZ,
                                             wh + 3 * SZ, wl + 3 * SZ,
                                             wid, pz, ph, s32, m, mdf, NB, 15, 0);
    tc_ur<<<dim3(NX, yb(NB)), 256, SMEMB>>>(mdf, wh, wl, rm, NB, 15, 0, wid, pr, m);
    // L1: nodes 7..14
    sumarm_k<7, 8><<<gb(NB * 8 * HDP / 2), 256>>>(wid, pr, rur, mlf, m, rm, s32, sf, af);
    tc_zhm<<<dim3(NX, yb(NB * 8)), 256, SMEMZ>>>(sf, af, wh + SZ, wl + SZ,
                                                 wh + 3 * SZ, wl + 3 * SZ,
                                                 wid, pz, ph, s32, m, mdf, NB * 8, 7, 3);
    tc_ur<<<dim3(NX, yb(NB * 8)), 256, SMEMB>>>(mdf, wh, wl, rm, NB * 8, 7, 3, wid, pr, m);
    // L2: nodes 3..6
    sumarm_k<3, 4><<<gb(NB * 4 * HDP / 2), 256>>>(wid, pr, rur, mlf, m, rm, s32, sf, af);
    tc_zhm<<<dim3(NX, yb(NB * 4)), 256, SMEMZ>>>(sf, af, wh + SZ, wl + SZ,
                                                 wh + 3 * SZ, wl + 3 * SZ,
                                                 wid, pz, ph, s32, m, mdf, NB * 4, 3, 2);
    tc_ur<<<dim3(NX, yb(NB * 4)), 256, SMEMB>>>(mdf, wh, wl, rm, NB * 4, 3, 2, wid, pr, m);
    // L3: nodes 1..2 (no ur needed)
    sumarm_k<1, 2><<<gb(NB * 2 * HDP / 2), 256>>>(wid, pr, rur, mlf, m, rm, s32, sf, af);
    tc_zhm<<<dim3(NX, yb(NB * 2)), 256, SMEMZ>>>(sf, af, wh + SZ, wl + SZ,
                                                 wh + 3 * SZ, wl + 3 * SZ,
                                                 wid, pz, ph, s32, m, mdf, NB * 2, 1, 1);
    // root
    sroot_k<<<gb(NB * HDP / 2), 256>>>(m, sf);
    tc_fin<<<dim3(NX, yb(NB)), 256, SMEMB>>>(sf, wh, wl, out, wid, pgt);
}

// round 16
// speedup vs baseline: 1.2292x; 1.2292x over previous
#include <cuda_runtime.h>
#include <cuda_fp16.h>
#include <math.h>
#include <cstdint>

#define HD 450
#define HDP 464
#define NTREE 32
#define NB 1024
#define NNODE (NB*NTREE)
#define NV 780

// ---------------- scratch ----------------
__device__ float g_pz [NV*HD];
__device__ float g_ph [NV*HD];
__device__ float g_pr [NV*HD];
__device__ float g_pgt[NV*HD];
__device__ float g_mlf[NV*HD];
__device__ float g_rur[NV*HD];
__device__ float g_m  [NNODE*HD];
__device__ float g_rm [NNODE*HD];
__device__ float g_zp [NB*8*HD];
__device__ float g_hp [NB*8*HD];
// fp16 activations (stride HDP, zero-padded)
__device__ __half g_ef  [NV*HDP];
__device__ __half g_mlff[NV*HDP];
__device__ __half g_sf  [NB*8*HDP];
__device__ __half g_af  [NB*8*HDP];
__device__ __half g_mdf [NB*8*HDP];
// fp16 weights, split hi/lo
__device__ __half g_wh  [8*HD*HDP];
__device__ __half g_wl  [8*HD*HDP];
// slots: 0 Wz_top, 1 Wz_bot, 2 Wh_top, 3 Wh_bot, 4 Wr, 5 Ur, 6 Wg_top, 7 Wg_bot

// ================= helpers =================
constexpr int BM = 128, BN = 64, BK = 64;
constexpr int NCHK = 8;
constexpr int ASTR = 72;
constexpr int BSTR = 72;
constexpr int STG  = BM*ASTR + 2*BK*BSTR;     // 18432 halfs/stage
constexpr int NSTG = 3;
constexpr int SMEMB = NSTG * STG * 2;         // 110592 B

__device__ __forceinline__ void ldm_x4(uint32_t* r, uint32_t addr) {
    asm volatile("ldmatrix.sync.aligned.m8n8.x4.shared.b16 {%0,%1,%2,%3}, [%4];"
                 : "=r"(r[0]), "=r"(r[1]), "=r"(r[2]), "=r"(r[3]) : "r"(addr));
}
__device__ __forceinline__ void ldm_x4t(uint32_t* r, uint32_t addr) {
    asm volatile("ldmatrix.sync.aligned.m8n8.x4.trans.shared.b16 {%0,%1,%2,%3}, [%4];"
                 : "=r"(r[0]), "=r"(r[1]), "=r"(r[2]), "=r"(r[3]) : "r"(addr));
}
__device__ __forceinline__ void mma_fp16(float* c, const uint32_t* a, const uint32_t* b) {
    asm volatile("mma.sync.aligned.m16n8k16.row.col.f32.f16.f16.f32 "
                 "{%0,%1,%2,%3}, {%4,%5,%6,%7}, {%8,%9}, {%0,%1,%2,%3};"
                 : "+f"(c[0]), "+f"(c[1]), "+f"(c[2]), "+f"(c[3])
                 : "r"(a[0]), "r"(a[1]), "r"(a[2]), "r"(a[3]), "r"(b[0]), "r"(b[1]));
}
__device__ __forceinline__ void cp16(uint32_t smem, const void* g) {
    asm volatile("cp.async.cg.shared.global [%0], [%1], 16;" :: "r"(smem), "l"(g));
}
#define CP_COMMIT() asm volatile("cp.async.commit_group;")
#define CP_WAITG1() asm volatile("cp.async.wait_group 1;" ::: "memory")

__device__ __forceinline__ uint32_t pack2h(float2 v) {
    __half2 h = __floats2half2_rn(v.x, v.y);
    return *(uint32_t*)&h;
}
__device__ __forceinline__ void split2h(float2 v, uint32_t& hi, uint32_t& lo) {
    __half2 h = __floats2half2_rn(v.x, v.y);
    float rx = v.x - __half2float(__low2half(h));
    float ry = v.y - __half2float(__high2half(h));
    __half2 l = __floats2half2_rn(rx, ry);
    hi = *(uint32_t*)&h;
    lo = *(uint32_t*)&l;
}
__device__ __forceinline__ float sigf(float x) { return 1.f / (1.f + expf(-x)); }

// ================= GEMM body (r14, proven 348us) =================
// EPI: 0 plain; 1 +bias; 3 rm=sig(pr[wp]+acc)*msrc (store rm);
//      4 relu(ptab[w0]+acc); 5 like 3 but no rm store, arm=rm+shfl -> afout[arow>>1]
template<int EPI>
__device__ __forceinline__ void gemm_body(
    const __half* __restrict__ Ag,
    const __half* __restrict__ Bgh, const __half* __restrict__ Bgl,
    const float* __restrict__ bias, float* __restrict__ C,
    int M, int lo, int lg,
    const int* __restrict__ wid, const float* __restrict__ ptab,
    const float* __restrict__ pr, const float* __restrict__ msrc,
    __half* __restrict__ afout)
{
    extern __shared__ __align__(16) __half smp[];
    const int tid = threadIdx.x;
    const int lane = tid & 31, wrp = tid >> 5;
    const int wm = wrp & 3, wn = wrp >> 2;
    const int n0 = blockIdx.x * BN, m0 = blockIdx.y * BM;

    float acc[2][4][4] = {};

    const int q = lane >> 3, r8 = lane & 7;
    const int arow_off = (q & 1) * 8 + r8;
    const int acol_off = (q >> 1) * 8;
    const int l16 = lane & 15;
    const int bcol8 = ((lane >> 4) & 1) * 8;

    auto fill = [&](int s, int c) {
        __half* Asm = smp + s * STG;
        __half* Bh  = Asm + BM * ASTR;
        __half* Bl  = Bh + BK * BSTR;
#pragma unroll
        for (int i = 0; i < 4; i++) {
            int idx = tid + i * 256;
            int row = idx >> 3, seg = idx & 7;
            int k = c * BK + seg * 8;
            int arow = m0 + row;
            __half* d = Asm + row * ASTR + seg * 8;
            if (arow < M && k <= HDP - 8)
                cp16((uint32_t)__cvta_generic_to_shared(d), Ag + (size_t)arow * HDP + k);
            else
                *(uint4*)d = make_uint4(0, 0, 0, 0);
        }
#pragma unroll
        for (int i = 0; i < 2; i++) {
            int idx = tid + i * 256;
            int kk = idx >> 3, seg = idx & 7;
            int k = c * BK + kk;
            int nj = n0 + seg * 8;
            __half* dh = Bh + kk * BSTR + seg * 8;
            __half* dl = Bl + kk * BSTR + seg * 8;
            if (k < HD && nj <= HDP - 8) {
                size_t gofs = (size_t)k * HDP + nj;
                cp16((uint32_t)__cvta_generic_to_shared(dh), Bgh + gofs);
                cp16((uint32_t)__cvta_generic_to_shared(dl), Bgl + gofs);
            } else {
                *(uint4*)dh = make_uint4(0, 0, 0, 0);
                *(uint4*)dl = make_uint4(0, 0, 0, 0);
            }
        }
    };

    fill(0, 0); CP_COMMIT();
    fill(1, 1); CP_COMMIT();
    for (int c = 0; c < NCHK; c++) {
        CP_WAITG1();
        __syncthreads();
        if (c + 2 < NCHK) fill((c + 2) % NSTG, c + 2);
        CP_COMMIT();

        const uint32_t sA  = (uint32_t)__cvta_generic_to_shared(smp + (c % NSTG) * STG);
        const uint32_t sBh = sA + BM * ASTR * 2;
        const uint32_t sBl = sBh + BK * BSTR * 2;
#pragma unroll
        for (int ks = 0; ks < 4; ks++) {
            uint32_t ah[2][4], bh[4][2], bl[4][2];
#pragma unroll
            for (int mf = 0; mf < 2; mf++) {
                int row = wm * 32 + mf * 16 + arow_off;
                int col = ks * 16 + acol_off;
                ldm_x4(ah[mf], sA + (uint32_t)(row * ASTR + col) * 2);
            }
#pragma unroll
            for (int nfp = 0; nfp < 2; nfp++) {
                uint32_t off = (uint32_t)((ks * 16 + l16) * BSTR
                                          + wn * 32 + nfp * 16 + bcol8) * 2;
                uint32_t r4[4];
                ldm_x4t(r4, sBh + off);
                bh[2 * nfp][0] = r4[0]; bh[2 * nfp][1] = r4[1];
                bh[2 * nfp + 1][0] = r4[2]; bh[2 * nfp + 1][1] = r4[3];
                ldm_x4t(r4, sBl + off);
                bl[2 * nfp][0] = r4[0]; bl[2 * nfp][1] = r4[1];
                bl[2 * nfp + 1][0] = r4[2]; bl[2 * nfp + 1][1] = r4[3];
            }
#pragma unroll
            for (int mf = 0; mf < 2; mf++)
#pragma unroll
                for (int nf = 0; nf < 4; nf++) {
                    mma_fp16(acc[mf][nf], ah[mf], bh[nf]);
                    mma_fp16(acc[mf][nf], ah[mf], bl[nf]);
                }
        }
    }

    const int gr = lane >> 2, gc = (lane & 3) * 2;
#pragma unroll
    for (int mf = 0; mf < 2; mf++) {
#pragma unroll
        for (int h = 0; h < 2; h++) {
            int arow = m0 + wm * 32 + mf * 16 + h * 8 + gr;
            if (arow >= M) continue;   // EPI5 callers guarantee M % 128 == 0
            int g = 0, wp = 0, w0 = 0;
            if constexpr (EPI == 3 || EPI == 5) {
                int t = arow >> lg, ci = lo + (arow & ((1 << lg) - 1));
                g  = t * NTREE + ci;
                wp = wid[t * NTREE + ((ci - 1) >> 1)];
            } else if constexpr (EPI == 4) {
                w0 = wid[arow * NTREE];
            }
#pragma unroll
            for (int nf = 0; nf < 4; nf++) {
                int j = n0 + wn * 32 + nf * 8 + gc;
                if (j >= HD) continue;   // uniform across shfl partners (j indep of gr)
                float vx = acc[mf][nf][h * 2];
                float vy = acc[mf][nf][h * 2 + 1];
                if constexpr (EPI == 0) {
                    *(float2*)&C[arow * HD + j] = make_float2(vx, vy);
                } else if constexpr (EPI == 1) {
                    float2 b = *(const float2*)&bias[j];
                    *(float2*)&C[arow * HD + j] = make_float2(vx + b.x, vy + b.y);
                } else if constexpr (EPI == 3) {
                    float2 pv = *(const float2*)&pr[wp * HD + j];
                    float2 mv = *(const float2*)&msrc[g * HD + j];
                    *(float2*)&C[g * HD + j] =
                        make_float2(sigf(pv.x + vx) * mv.x, sigf(pv.y + vy) * mv.y);
                } else if constexpr (EPI == 5) {
                    float2 pv = *(const float2*)&pr[wp * HD + j];
                    float2 mv = *(const float2*)&msrc[g * HD + j];
                    float rx = sigf(pv.x + vx) * mv.x;
                    float ry = sigf(pv.y + vy) * mv.y;
                    float ox = rx + __shfl_xor_sync(0xffffffffu, rx, 4);
                    float oy = ry + __shfl_xor_sync(0xffffffffu, ry, 4);
                    if ((gr & 1) == 0) {   // even child row holds parent
                        int prow = arow >> 1;
                        *(uint32_t*)&afout[prow * HDP + j] = pack2h(make_float2(ox, oy));
                    }
                } else { // EPI == 4
                    float2 pv = *(const float2*)&ptab[w0 * HD + j];
                    *(float2*)&C[arow * HD + j] =
                        make_float2(fmaxf(pv.x + vx, 0.f), fmaxf(pv.y + vy, 0.f));
                }
            }
        }
    }
}

// ================= GEMM wrappers =================
__global__ __launch_bounds__(256) void tc_vocab(
    const __half* ef, const __half* wh, const __half* wl,
    const float* bz, const float* bh_, const float* bU, const float* bg,
    float* pz, float* ph_, float* pr, float* pgt)
{
    const int SZ = HD * HDP;
    const float* b; float* C; int slot;
    switch (blockIdx.z) {
        case 0:  slot = 0; b = bz;  C = pz;  break;
        case 1:  slot = 2; b = bh_; C = ph_; break;
        case 2:  slot = 4; b = bU;  C = pr;  break;
        default: slot = 6; b = bg;  C = pgt; break;
    }
    gemm_body<1>(ef, wh + slot * SZ, wl + slot * SZ, b, C,
                 NV, 0, 0, nullptr, nullptr, nullptr, nullptr, nullptr);
}

__global__ __launch_bounds__(256) void tc_rur(
    const __half* mlff, const __half* wh, const __half* wl, float* rur)
{
    const int SZ = HD * HDP;
    gemm_body<0>(mlff, wh + 5 * SZ, wl + 5 * SZ, nullptr, rur,
                 NV, 0, 0, nullptr, nullptr, nullptr, nullptr, nullptr);
}

// combined z + h for level 0 (arm already known from s0)
__global__ __launch_bounds__(256) void tc_zh(
    const __half* sf, const __half* af,
    const __half* wh, const __half* wl,
    float* zp, float* hp, int M)
{
    const int SZ = HD * HDP;
    if (blockIdx.z == 0)
        gemm_body<0>(sf, wh + 1 * SZ, wl + 1 * SZ, nullptr, zp,
                     M, 0, 0, nullptr, nullptr, nullptr, nullptr, nullptr);
    else
        gemm_body<0>(af, wh + 3 * SZ, wl + 3 * SZ, nullptr, hp,
                     M, 0, 0, nullptr, nullptr, nullptr, nullptr, nullptr);
}

// combined ur (slice 0) + next-level z (slice 1)
// FUSE=1: ur epilogue EPI5 (arm fused into af, no rm store)
template<int FUSE>
__global__ __launch_bounds__(256) void tc_urz(
    const __half* mdf, const __half* sf,
    const __half* wh, const __half* wl,
    float* rm, float* zp, __half* af,
    int Mur, int Mz, int lo, int lg,
    const int* wid, const float* pr, const float* msrc)
{
    const int SZ = HD * HDP;
    if (blockIdx.z == 0) {
        if ((int)blockIdx.y * BM >= Mur) return;
        if constexpr (FUSE)
            gemm_body<5>(mdf, wh + 5 * SZ, wl + 5 * SZ, nullptr, rm,
                         Mur, lo, lg, wid, nullptr, pr, msrc, af);
        else
            gemm_body<3>(mdf, wh + 5 * SZ, wl + 5 * SZ, nullptr, rm,
                         Mur, lo, lg, wid, nullptr, pr, msrc, nullptr);
    } else {
        if ((int)blockIdx.y * BM >= Mz) return;
        gemm_body<0>(sf, wh + 1 * SZ, wl + 1 * SZ, nullptr, zp,
                     Mz, 0, 0, nullptr, nullptr, nullptr, nullptr, nullptr);
    }
}

// h-only GEMM (arm @ Wh_bot)
__global__ __launch_bounds__(256) void tc_h(
    const __half* af, const __half* wh, const __half* wl, float* hp, int M)
{
    const int SZ = HD * HDP;
    gemm_body<0>(af, wh + 3 * SZ, wl + 3 * SZ, nullptr, hp,
                 M, 0, 0, nullptr, nullptr, nullptr, nullptr, nullptr);
}

__global__ __launch_bounds__(256) void tc_fin(
    const __half* sf, const __half* wh, const __half* wl,
    float* out, const int* wid, const float* pgt)
{
    const int SZ = HD * HDP;
    gemm_body<4>(sf, wh + 7 * SZ, wl + 7 * SZ, nullptr, out,
                 NB, 0, 0, wid, pgt, nullptr, nullptr, nullptr);
}

// ================= producers =================
__global__ void preconv_k(const float* __restrict__ Wz, const float* __restrict__ Wh,
                          const float* __restrict__ Wr, const float* __restrict__ Ur,
                          const float* __restrict__ Wg,
                          __half* __restrict__ wh, __half* __restrict__ wl)
{
    int idx = blockIdx.x * blockDim.x + threadIdx.x;
    const int SZ2 = HD * HDP / 2;
    if (idx >= 8 * SZ2) return;
    int slot = idx / SZ2, off = idx - slot * SZ2;
    int k = off / (HDP / 2), j = (off - k * (HDP / 2)) * 2;
    float2 v = make_float2(0.f, 0.f);
    if (j < HD) {
        int src = k * HD + j;
        const int WSZ = HD * HD;
        switch (slot) {
            case 0:  v = *(const float2*)&Wz[src];       break;
            case 1:  v = *(const float2*)&Wz[WSZ + src]; break;
            case 2:  v = *(const float2*)&Wh[src];       break;
            case 3:  v = *(const float2*)&Wh[WSZ + src]; break;
            case 4:  v = *(const float2*)&Wr[src];       break;
            case 5:  v = *(const float2*)&Ur[src];       break;
            case 6:  v = *(const float2*)&Wg[src];       break;
            default: v = *(const float2*)&Wg[WSZ + src]; break;
        }
    }
    uint32_t hi, lo;
    split2h(v, hi, lo);
    int d = slot * HD * HDP + k * HDP + j;
    *(uint32_t*)&wh[d] = hi;
    *(uint32_t*)&wl[d] = lo;
}

__global__ void esplit_k(const float* __restrict__ emb, __half* __restrict__ ef)
{
    int idx = blockIdx.x * blockDim.x + threadIdx.x;
    if (idx >= NV * HDP / 2) return;
    int row = idx / (HDP / 2), j = (idx - row * (HDP / 2)) * 2;
    float2 v = (j < HD) ? *(const float2*)&emb[row * HD + j] : make_float2(0.f, 0.f);
    *(uint32_t*)&ef[row * HDP + j] = pack2h(v);
}

__global__ void mleaf_k(const float* __restrict__ pz, const float* __restrict__ ph,
                        float* __restrict__ mlf, __half* __restrict__ mlff)
{
    int idx = blockIdx.x * blockDim.x + threadIdx.x;
    if (idx >= NV * HDP / 2) return;
    int row = idx / (HDP / 2), j = (idx - row * (HDP / 2)) * 2;
    float2 v = make_float2(0.f, 0.f);
    if (j < HD) {
        int s = row * HD + j;
        float2 a = *(const float2*)&pz[s];
        float2 b = *(const float2*)&ph[s];
        v.x = tanhf(b.x) * sigf(a.x);
        v.y = tanhf(b.y) * sigf(a.y);
        *(float2*)&mlf[s] = v;
    }
    *(uint32_t*)&mlff[row * HDP + j] = pack2h(v);
}

__global__ void s0_k(const int* __restrict__ wid,
                     const float* __restrict__ pr, const float* __restrict__ rur,
                     const float* __restrict__ mlf,
                     __half* __restrict__ sf, __half* __restrict__ af)
{
    int idx = blockIdx.x * blockDim.x + threadIdx.x;
    if (idx >= NB * (HDP / 2)) return;
    int t = idx / (HDP / 2), j = (idx - t * (HDP / 2)) * 2;
    float2 s = make_float2(0.f, 0.f), a = s;
    if (j < HD) {
        int w15 = wid[t * NTREE + 15];
        int w31 = wid[t * NTREE + 31];
        s = *(const float2*)&mlf[w31 * HD + j];
        float2 ru = *(const float2*)&rur[w31 * HD + j];
        float2 pv = *(const float2*)&pr[w15 * HD + j];
        a = make_float2(sigf(pv.x + ru.x) * s.x, sigf(pv.y + ru.y) * s.y);
    }
    int d = t * HDP + j;
    *(uint32_t*)&sf[d] = pack2h(s);
    *(uint32_t*)&af[d] = pack2h(a);
}

// prep: m_new for interior children of parents [PLO,PLO+PCNT), emit m fp32
// + mdf fp16 (child rows) + parent s (sf, fp16). Writes pad zeros for mdf.
template<int PLO, int PCNT, int CLO, int CCNT, int WMD>
__global__ void prep_k(const int* __restrict__ wid,
                       const float* __restrict__ pz, const float* __restrict__ ph,
                       const float* __restrict__ zp, const float* __restrict__ hp,
                       const float* __restrict__ mlf,
                       float* __restrict__ m, __half* __restrict__ mdf,
                       __half* __restrict__ sf)
{
    int idx = blockIdx.x * blockDim.x + threadIdx.x;
    if (idx >= NB * PCNT * (HDP / 2)) return;
    int row = idx / (HDP / 2), j = (idx - row * (HDP / 2)) * 2;
    int t = row / PCNT;
    int p = PLO + (row - t * PCNT);
    float2 msum = make_float2(0.f, 0.f);
    if (j < HD) {
#pragma unroll
        for (int ch = 0; ch < 2; ch++) {
            int c = 2 * p + 1 + ch;
            float2 mc;
            if (c >= 16) {
                int w = wid[t * NTREE + c];
                mc = *(const float2*)&mlf[w * HD + j];
            } else {
                int crow = t * CCNT + (c - CLO);
                int w = wid[t * NTREE + c];
                float2 pzv = *(const float2*)&pz[w * HD + j];
                float2 phv = *(const float2*)&ph[w * HD + j];
                float2 zpv = *(const float2*)&zp[crow * HD + j];
                float2 hpv = *(const float2*)&hp[crow * HD + j];
                int gc1 = 2 * c + 1, gc2 = 2 * c + 2;
                float2 s;
                if (gc1 < 16)  s = *(const float2*)&m[(t * NTREE + gc1) * HD + j];
                else           s = *(const float2*)&mlf[wid[t * NTREE + gc1] * HD + j];
                if (gc2 < NTREE) {
                    float2 s2;
                    if (gc2 < 16) s2 = *(const float2*)&m[(t * NTREE + gc2) * HD + j];
                    else          s2 = *(const float2*)&mlf[wid[t * NTREE + gc2] * HD + j];
                    s.x += s2.x; s.y += s2.y;
                }
                float zx = sigf(pzv.x + zpv.x);
                float zy = sigf(pzv.y + zpv.y);
                mc.x = (1.f - zx) * s.x + zx * tanhf(phv.x + hpv.x);
                mc.y = (1.f - zy) * s.y + zy * tanhf(phv.y + hpv.y);
                *(float2*)&m[(t * NTREE + c) * HD + j] = mc;
                if (WMD)
                    *(uint32_t*)&mdf[crow * HDP + j] = pack2h(mc);
            }
            msum.x += mc.x; msum.y += mc.y;
        }
    } else if (WMD) {
#pragma unroll
        for (int ch = 0; ch < 2; ch++) {
            int c = 2 * p + 1 + ch;
            if (c < 16) {
                int crow = t * CCNT + (c - CLO);
                *(uint32_t*)&mdf[crow * HDP + j] = 0;
            }
        }
    }
    *(uint32_t*)&sf[row * HDP + j] = pack2h(msum);
}

// arm for nodes 7..14 (mixed leaf/interior children; only L1 needs this path)
__global__ void armsplit78_k(const int* __restrict__ wid,
                             const float* __restrict__ pr, const float* __restrict__ rur,
                             const float* __restrict__ mlf, const float* __restrict__ rm,
                             __half* __restrict__ af)
{
    int idx = blockIdx.x * blockDim.x + threadIdx.x;
    if (idx >= NB * 8 * (HDP / 2)) return;
    int row = idx / (HDP / 2), j = (idx - row * (HDP / 2)) * 2;
    int t = row >> 3;
    int n = 7 + (row & 7);
    float2 a = make_float2(0.f, 0.f);
    if (j < HD) {
        int wp = wid[t * NTREE + n];
#pragma unroll
        for (int ch = 0; ch < 2; ch++) {
            int c = 2 * n + 1 + ch;
            if (c < 16) {
                float2 rv = *(const float2*)&rm[(t * NTREE + c) * HD + j];
                a.x += rv.x; a.y += rv.y;
            } else {
                int w = wid[t * NTREE + c];
                float2 ru = *(const float2*)&rur[w * HD + j];
                float2 pv = *(const float2*)&pr[wp * HD + j];
                float2 mv = *(const float2*)&mlf[w * HD + j];
                a.x += sigf(pv.x + ru.x) * mv.x;
                a.y += sigf(pv.y + ru.y) * mv.y;
            }
        }
    }
    *(uint32_t*)&af[row * HDP + j] = pack2h(a);
}

// ================= launch =================
extern "C" void kernel_launch(void* const* d_in, const int* in_sizes, int n_in,
                              void* d_out, int out_size)
{
    const int*   wid = (const int*)  d_in[0];
    const float* emb = (const float*)d_in[1];
    const float* Wz  = (const float*)d_in[2];
    const float* bz  = (const float*)d_in[3];
    const float* Wr  = (const float*)d_in[4];
    const float* Ur  = (const float*)d_in[5];
    const float* bU  = (const float*)d_in[6];
    const float* Wh  = (const float*)d_in[7];
    const float* bh  = (const float*)d_in[8];
    const float* Wg  = (const float*)d_in[9];
    const float* bg  = (const float*)d_in[10];
    float* out = (float*)d_out;

    float *pz, *ph, *pr, *pgt, *mlf, *rur, *m, *rm, *zp, *hp;
    __half *ef, *mlff, *sf, *af, *mdf, *wh, *wl;
    cudaGetSymbolAddress((void**)&pz,  g_pz);
    cudaGetSymbolAddress((void**)&ph,  g_ph);
    cudaGetSymbolAddress((void**)&pr,  g_pr);
    cudaGetSymbolAddress((void**)&pgt, g_pgt);
    cudaGetSymbolAddress((void**)&mlf, g_mlf);
    cudaGetSymbolAddress((void**)&rur, g_rur);
    cudaGetSymbolAddress((void**)&m,   g_m);
    cudaGetSymbolAddress((void**)&rm,  g_rm);
    cudaGetSymbolAddress((void**)&zp,  g_zp);
    cudaGetSymbolAddress((void**)&hp,  g_hp);
    cudaGetSymbolAddress((void**)&ef,  g_ef);
    cudaGetSymbolAddress((void**)&mlff, g_mlff);
    cudaGetSymbolAddress((void**)&sf,  g_sf);
    cudaGetSymbolAddress((void**)&af,  g_af);
    cudaGetSymbolAddress((void**)&mdf, g_mdf);
    cudaGetSymbolAddress((void**)&wh,  g_wh);
    cudaGetSymbolAddress((void**)&wl,  g_wl);

    cudaFuncSetAttribute(tc_vocab,  cudaFuncAttributeMaxDynamicSharedMemorySize, SMEMB);
    cudaFuncSetAttribute(tc_rur,    cudaFuncAttributeMaxDynamicSharedMemorySize, SMEMB);
    cudaFuncSetAttribute(tc_zh,     cudaFuncAttributeMaxDynamicSharedMemorySize, SMEMB);
    cudaFuncSetAttribute(tc_urz<0>, cudaFuncAttributeMaxDynamicSharedMemorySize, SMEMB);
    cudaFuncSetAttribute(tc_urz<1>, cudaFuncAttributeMaxDynamicSharedMemorySize, SMEMB);
    cudaFuncSetAttribute(tc_h,      cudaFuncAttributeMaxDynamicSharedMemorySize, SMEMB);
    cudaFuncSetAttribute(tc_fin,    cudaFuncAttributeMaxDynamicSharedMemorySize, SMEMB);

    const int NX = (HD + BN - 1) / BN;   // 8
    auto yb = [](int M) { return (M + BM - 1) / BM; };
    auto gb = [](int n) { return (n + 255) / 256; };
    auto mx = [](int a, int b) { return a > b ? a : b; };

    // prelude
    preconv_k<<<gb(8 * HD * HDP / 2), 256>>>(Wz, Wh, Wr, Ur, Wg, wh, wl);
    esplit_k<<<gb(NV * HDP / 2), 256>>>(emb, ef);
    tc_vocab<<<dim3(NX, yb(NV), 4), 256, SMEMB>>>(ef, wh, wl,
                                                  bz, bh, bU, bg, pz, ph, pr, pgt);
    mleaf_k<<<gb(NV * HDP / 2), 256>>>(pz, ph, mlf, mlff);
    tc_rur<<<dim3(NX, yb(NV)), 256, SMEMB>>>(mlff, wh, wl, rur);

    // L0: node 15
    s0_k<<<gb(NB * HDP / 2), 256>>>(wid, pr, rur, mlf, sf, af);
    tc_zh<<<dim3(NX, yb(NB), 2), 256, SMEMB>>>(sf, af, wh, wl, zp, hp, NB);
    // L1: prep (m15 + s[7..14]) -> [ur15 + z(7..14)] -> armsplit -> h(7..14)
    prep_k<7, 8, 15, 1, 1><<<gb(NB * 8 * HDP / 2), 256>>>(wid, pz, ph, zp, hp, mlf,
                                                          m, mdf, sf);
    tc_urz<0><<<dim3(NX, mx(yb(NB), yb(NB * 8)), 2), 256, SMEMB>>>(
        mdf, sf, wh, wl, rm, zp, af, NB, NB * 8, 15, 0, wid, pr, m);
    armsplit78_k<<<gb(NB * 8 * HDP / 2), 256>>>(wid, pr, rur, mlf, rm, af);
    tc_h<<<dim3(NX, yb(NB * 8)), 256, SMEMB>>>(af, wh, wl, hp, NB * 8);
    // L2: prep (m[7..14] + s[3..6]) -> [ur(7..14, arm fused -> af[1,2-level parents 3..6]) + z(3..6)] -> h(3..6)
    prep_k<3, 4, 7, 8, 1><<<gb(NB * 4 * HDP / 2), 256>>>(wid, pz, ph, zp, hp, mlf,
                                                         m, mdf, sf);
    tc_urz<1><<<dim3(NX, mx(yb(NB * 8), yb(NB * 4)), 2), 256, SMEMB>>>(
        mdf, sf, wh, wl, rm, zp, af, NB * 8, NB * 4, 7, 3, wid, pr, m);
    tc_h<<<dim3(NX, yb(NB * 4)), 256, SMEMB>>>(af, wh, wl, hp, NB * 4);
    // L3: prep (m[3..6] + s[1..2]) -> [ur(3..6, arm fused -> parents 1..2) + z(1..2)] -> h(1..2)
    prep_k<1, 2, 3, 4, 1><<<gb(NB * 2 * HDP / 2), 256>>>(wid, pz, ph, zp, hp, mlf,
                                                         m, mdf, sf);
    tc_urz<1><<<dim3(NX, mx(yb(NB * 4), yb(NB * 2)), 2), 256, SMEMB>>>(
        mdf, sf, wh, wl, rm, zp, af, NB * 4, NB * 2, 3, 2, wid, pr, m);
    tc_h<<<dim3(NX, yb(NB * 2)), 256, SMEMB>>>(af, wh, wl, hp, NB * 2);
    // root: prep (m[1..2] + s_root) -> fin
    prep_k<0, 1, 1, 2, 0><<<gb(NB * HDP / 2), 256>>>(wid, pz, ph, zp, hp, mlf,
                                                     m, mdf, sf);
    tc_fin<<<dim3(NX, yb(NB)), 256, SMEMB>>>(sf, wh, wl, out, wid, pgt);
}